// round 15
// baseline (speedup 1.0000x reference)
#include <cuda_runtime.h>
#include <math.h>

#define H    1024
#define V    50257
#define S    4096
#define G3   3072
#define NB   148
#define NT   1024
#define NWARP (NB * 32)
#define ROWS_PB 340            // ceil(V/NB) for the final write pass
#define SCH 28                 // ceil(S/NB)
#define ICH 7                  // ceil(H/NB)

// ---------------- global scratch ----------------
__device__ float g_gi0[G3];
__device__ float g_gh0[G3];
__device__ float g_gi1[G3];
__device__ float g_gh1[G3];
__device__ float g_v[H];
__device__ float g_energ[S];
__device__ float g_ctx[H];
__device__ float g_logits[V + 32];
__device__ float g_part[2 * NB];
__device__ unsigned g_q;                  // phase-6 queue; reset at start, used after barrier 5
__device__ unsigned g_count;
__device__ volatile unsigned g_epoch;

// ---------------- software grid barrier ----------------
__device__ __forceinline__ void gsync() {
    __syncthreads();
    if (threadIdx.x == 0) {
        __threadfence();
        unsigned e = g_epoch;
        if (atomicAdd(&g_count, 1) == (unsigned)(gridDim.x - 1)) {
            g_count = 0;
            __threadfence();
            g_epoch = e + 1;
        } else {
            while (g_epoch == e) __nanosleep(32);
        }
        __threadfence();
    }
    __syncthreads();
}

__device__ __forceinline__ float sigmoidf_(float x) {
    return 1.f / (1.f + __expf(-x));
}

// warp dot, 4 streams; CS=true -> evict-first loads for single-use weights
template<bool CS>
__device__ __forceinline__ float wdot(const float4* __restrict__ w,
                                      const float4* __restrict__ x,
                                      int n4, int lane) {
    float s0 = 0.f, s1 = 0.f, s2 = 0.f, s3 = 0.f;
#pragma unroll 4
    for (int i = lane; i < n4; i += 128) {
        float4 a0 = CS ? __ldcs(w + i)      : __ldg(w + i);
        float4 a1 = CS ? __ldcs(w + i + 32) : __ldg(w + i + 32);
        float4 a2 = CS ? __ldcs(w + i + 64) : __ldg(w + i + 64);
        float4 a3 = CS ? __ldcs(w + i + 96) : __ldg(w + i + 96);
        float4 b0 = x[i];
        float4 b1 = x[i + 32];
        float4 b2 = x[i + 64];
        float4 b3 = x[i + 96];
        s0 = fmaf(a0.x, b0.x, fmaf(a0.y, b0.y, fmaf(a0.z, b0.z, fmaf(a0.w, b0.w, s0))));
        s1 = fmaf(a1.x, b1.x, fmaf(a1.y, b1.y, fmaf(a1.z, b1.z, fmaf(a1.w, b1.w, s1))));
        s2 = fmaf(a2.x, b2.x, fmaf(a2.y, b2.y, fmaf(a2.z, b2.z, fmaf(a2.w, b2.w, s2))));
        s3 = fmaf(a3.x, b3.x, fmaf(a3.y, b3.y, fmaf(a3.z, b3.z, fmaf(a3.w, b3.w, s3))));
    }
    float s = (s0 + s1) + (s2 + s3);
#pragma unroll
    for (int o = 16; o; o >>= 1) s += __shfl_xor_sync(0xffffffffu, s, o);
    return s;
}

__global__ void __launch_bounds__(NT, 1)
decoder_kernel(const int* __restrict__ word, const float* __restrict__ lctx,
               const float* __restrict__ lh, const float* __restrict__ enc,
               const float* __restrict__ emb,
               const float* __restrict__ Wih0, const float* __restrict__ Whh0,
               const float* __restrict__ bih0, const float* __restrict__ bhh0,
               const float* __restrict__ Wih1, const float* __restrict__ Whh1,
               const float* __restrict__ bih1, const float* __restrict__ bhh1,
               const float* __restrict__ Wattn, const float* __restrict__ Wout,
               const float* __restrict__ bout, float* __restrict__ out) {
    __shared__ float sh_in[2 * H];
    __shared__ float sh_lh[2 * H];
    __shared__ float sh_h0[H];            // h0; later stages v
    __shared__ float sh_xcat[2 * H];      // [h1 ; ctx]
    __shared__ float sh_a[SCH];
    __shared__ float sh_red[32];
    __shared__ float sh_red2[32];
    __shared__ float sh_bc[2];

    const int t = threadIdx.x;
    const int lane = t & 31;
    const int wid = t >> 5;
    const int b = blockIdx.x;
    const int gw = b * 32 + wid;

    {
        int w0 = word[0];
        sh_in[t]     = emb[(size_t)w0 * H + t];
        sh_in[H + t] = lctx[t];
        sh_lh[t]     = lh[t];
        sh_lh[H + t] = lh[H + t];
    }
    if (b == 0) {
        g_v[t] = 0.f;
        g_ctx[t] = 0.f;
        if (t == 0) g_q = 0;              // first use after barrier 5 (proven safe in R12)
    }
    __syncthreads();

    // ---------- phase 1: equal 12KB units, one pass (static, proven) ------
    // units 0..3071:   gi0 row u (8KB) + gh0 row u (4KB)
    // units 3072..4095: gh1 rows 3k,3k+1,3k+2 (3 x 4KB)
    if (gw < G3) {
        float s = wdot<true>((const float4*)(Wih0 + (size_t)gw * 2 * H),
                             (const float4*)sh_in, 512, lane);
        if (!lane) g_gi0[gw] = s + bih0[gw];
        float s2 = wdot<true>((const float4*)(Whh0 + (size_t)gw * H),
                              (const float4*)sh_lh, 256, lane);
        if (!lane) g_gh0[gw] = s2 + bhh0[gw];
    } else if (gw < 4096) {
        int r0 = 3 * (gw - G3);
#pragma unroll
        for (int j = 0; j < 3; j++) {
            int r = r0 + j;
            float s = wdot<true>((const float4*)(Whh1 + (size_t)r * H),
                                 (const float4*)(sh_lh + H), 256, lane);
            if (!lane) g_gh1[r] = s + bhh1[r];
        }
    }
    gsync();   // barrier 1

    // ---------- phase 2: h0 recompute (local); gi1 = W_ih1 @ h0 ----------
    {
        float r_ = sigmoidf_(g_gi0[t] + g_gh0[t]);
        float z  = sigmoidf_(g_gi0[H + t] + g_gh0[H + t]);
        float n  = tanhf(g_gi0[2 * H + t] + r_ * g_gh0[2 * H + t]);
        float h  = (1.f - z) * n + z * sh_lh[t];
        sh_h0[t] = h;
        if (b == 0) out[V + H + t] = h;   // hidden[0]
    }
    __syncthreads();
    if (gw < G3) {
        float s = wdot<true>((const float4*)(Wih1 + (size_t)gw * H),
                             (const float4*)sh_h0, 256, lane);
        if (!lane) g_gi1[gw] = s + bih1[gw];
    }
    gsync();   // barrier 2

    // ---------- phase 3: h1 recompute (local); v partials -----------------
    {
        float r_ = sigmoidf_(g_gi1[t] + g_gh1[t]);
        float z  = sigmoidf_(g_gi1[H + t] + g_gh1[H + t]);
        float n  = tanhf(g_gi1[2 * H + t] + r_ * g_gh1[2 * H + t]);
        float h  = (1.f - z) * n + z * sh_lh[H + t];
        sh_xcat[t] = h;
        if (b == 0) out[V + 2 * H + t] = h; // hidden[1]
    }
    __syncthreads();
    {
        float acc = 0.f;
        int i0 = b * ICH;
#pragma unroll
        for (int k = 0; k < ICH; k++) {
            int i = i0 + k;
            if (i < H) acc = fmaf(Wattn[(size_t)i * H + t], sh_xcat[i], acc);
        }
        atomicAdd(&g_v[t], acc);
    }
    gsync();   // barrier 3

    // ---------- phase 4: energies (enc stays L2-resident: no .cs) ---------
    sh_h0[t] = g_v[t];
    __syncthreads();
    if (gw < S) {
        float s = wdot<false>((const float4*)(enc + (size_t)gw * H),
                              (const float4*)sh_h0, 256, lane);
        if (!lane) g_energ[gw] = s;
    }
    gsync();   // barrier 4

    // ---------- phase 5: softmax (redundant) + ctx partials ---------------
    {
        float m = -INFINITY;
        for (int i = t; i < S; i += NT) m = fmaxf(m, g_energ[i]);
#pragma unroll
        for (int o = 16; o; o >>= 1) m = fmaxf(m, __shfl_xor_sync(0xffffffffu, m, o));
        if (!lane) sh_red[wid] = m;
        __syncthreads();
        if (wid == 0) {
            m = sh_red[lane];
#pragma unroll
            for (int o = 16; o; o >>= 1) m = fmaxf(m, __shfl_xor_sync(0xffffffffu, m, o));
            if (!lane) sh_bc[0] = m;
        }
        __syncthreads();
        float bmax = sh_bc[0];
        float sum = 0.f;
        for (int i = t; i < S; i += NT) sum += __expf(g_energ[i] - bmax);
#pragma unroll
        for (int o = 16; o; o >>= 1) sum += __shfl_xor_sync(0xffffffffu, sum, o);
        if (!lane) sh_red[wid] = sum;
        __syncthreads();
        if (wid == 0) {
            sum = sh_red[lane];
#pragma unroll
            for (int o = 16; o; o >>= 1) sum += __shfl_xor_sync(0xffffffffu, sum, o);
            if (!lane) sh_bc[1] = sum;
        }
        __syncthreads();
        float inv = 1.f / sh_bc[1];
        int s0 = b * SCH;
        if (t < SCH && s0 + t < S) {
            float a = __expf(g_energ[s0 + t] - bmax) * inv;
            sh_a[t] = a;
            out[V + 3 * H + s0 + t] = a;  // attn_weights
        }
        __syncthreads();
        float acc = 0.f;
#pragma unroll
        for (int k = 0; k < SCH; k++) {
            int s = s0 + k;
            if (s < S) acc = fmaf(sh_a[k], enc[(size_t)s * H + t], acc);
        }
        atomicAdd(&g_ctx[t], acc);
    }
    gsync();   // barrier 5

    // ---------- phase 6: logits, per-warp steal (pop-ahead) + online LSE --
    sh_xcat[H + t] = g_ctx[t];
    if (b == 0) out[V + t] = g_ctx[t];    // context
    __syncthreads();
    float lm = -INFINITY, lsum = 0.f;
    {
        int first = 0;
        if (lane == 0) first = (int)atomicAdd(&g_q, 1u);
        int cur = __shfl_sync(0xffffffffu, first, 0);
        while (cur < V) {
            int nxt = 0;
            if (lane == 0) nxt = (int)atomicAdd(&g_q, 1u);  // hides under the dot
            float s = wdot<true>((const float4*)(Wout + (size_t)cur * 2 * H),
                                 (const float4*)sh_xcat, 512, lane) + bout[cur];
            if (!lane) g_logits[cur] = s;
            float mn = fmaxf(lm, s);
            lsum = lsum * __expf(lm - mn) + __expf(s - mn);
            lm = mn;
            cur = __shfl_sync(0xffffffffu, nxt, 0);
        }
    }
    // block-level (max,sum) merge over 32 warps
    if (!lane) { sh_red[wid] = lm; sh_red2[wid] = lsum; }
    __syncthreads();
    if (wid == 0) {
        float m = sh_red[lane], sacc = sh_red2[lane];
#pragma unroll
        for (int o = 16; o; o >>= 1) {
            float mo = __shfl_xor_sync(0xffffffffu, m, o);
            float so = __shfl_xor_sync(0xffffffffu, sacc, o);
            float mn = fmaxf(m, mo);
            sacc = sacc * __expf(m - mn) + so * __expf(mo - mn);
            m = mn;
        }
        if (!lane) { g_part[2 * b] = m; g_part[2 * b + 1] = sacc; }
    }
    gsync();   // barrier 6

    // ---------- phase 7: merge LSE (redundant); write log_softmax ---------
    {
        if (wid == 0) {
            float m = -INFINITY, sacc = 0.f;
            for (int i = lane; i < NB; i += 32) {
                float mi = g_part[2 * i], si = g_part[2 * i + 1];
                float mn = fmaxf(m, mi);
                sacc = sacc * __expf(m - mn) + si * __expf(mi - mn);
                m = mn;
            }
#pragma unroll
            for (int o = 16; o; o >>= 1) {
                float mo = __shfl_xor_sync(0xffffffffu, m, o);
                float so = __shfl_xor_sync(0xffffffffu, sacc, o);
                float mn = fmaxf(m, mo);
                sacc = sacc * __expf(m - mn) + so * __expf(mo - mn);
                m = mn;
            }
            if (!lane) { sh_bc[0] = m; sh_bc[1] = logf(sacc); }
        }
        __syncthreads();
        float mm = sh_bc[0], ls = sh_bc[1];
        const int base = b * ROWS_PB;
        const int nrows = min(ROWS_PB, V - base);
        for (int i = t; i < nrows; i += NT)
            out[base + i] = g_logits[base + i] - mm - ls;
    }
}

// ---------------- launch ----------------
extern "C" void kernel_launch(void* const* d_in, const int* in_sizes, int n_in,
                              void* d_out, int out_size) {
    const int*   word  = (const int*)  d_in[0];
    const float* lctx  = (const float*)d_in[1];
    const float* lh    = (const float*)d_in[2];
    const float* enc   = (const float*)d_in[3];
    const float* emb   = (const float*)d_in[4];
    const float* Wih0  = (const float*)d_in[5];
    const float* Whh0  = (const float*)d_in[6];
    const float* bih0  = (const float*)d_in[7];
    const float* bhh0  = (const float*)d_in[8];
    const float* Wih1  = (const float*)d_in[9];
    const float* Whh1  = (const float*)d_in[10];
    const float* bih1  = (const float*)d_in[11];
    const float* bhh1  = (const float*)d_in[12];
    const float* Wattn = (const float*)d_in[13];
    // d_in[14] = b_attn: cancels in softmax
    const float* Wout  = (const float*)d_in[15];
    const float* bout  = (const float*)d_in[16];
    float* out = (float*)d_out;

    decoder_kernel<<<NB, NT>>>(word, lctx, lh, enc, emb,
                               Wih0, Whh0, bih0, bhh0,
                               Wih1, Whh1, bih1, bhh1,
                               Wattn, Wout, bout, out);
}

// round 16
// speedup vs baseline: 1.2788x; 1.2788x over previous
#include <cuda_runtime.h>
#include <math.h>

#define H    1024
#define V    50257
#define S    4096
#define G3   3072
#define NB   148
#define NT   1024
#define NWARP (NB * 32)
#define ROWS_PB 340            // ceil(V/NB) for the final write pass
#define SCH 28                 // ceil(S/NB)
#define ICH 7                  // ceil(H/NB)
#define NTILES6 1571           // ceil(V/32) logits tiles

// ---------------- global scratch ----------------
__device__ float g_gi0[G3];
__device__ float g_gh0[G3];
__device__ float g_gi1[G3];
__device__ float g_gh1[G3];
__device__ float g_v[H];
__device__ float g_energ[S];
__device__ float g_ctx[H];
__device__ float g_logits[V + 32];
__device__ float g_part[2 * NB];
__device__ unsigned g_q;                  // phase-6 queue; reset at start, first use after barrier 5
__device__ unsigned g_count;
__device__ volatile unsigned g_epoch;

// ---------------- software grid barrier ----------------
__device__ __forceinline__ void gsync() {
    __syncthreads();
    if (threadIdx.x == 0) {
        __threadfence();
        unsigned e = g_epoch;
        if (atomicAdd(&g_count, 1) == (unsigned)(gridDim.x - 1)) {
            g_count = 0;
            __threadfence();
            g_epoch = e + 1;
        } else {
            while (g_epoch == e) __nanosleep(32);
        }
        __threadfence();
    }
    __syncthreads();
}

__device__ __forceinline__ float sigmoidf_(float x) {
    return 1.f / (1.f + __expf(-x));
}

// warp dot, 4 streams; CS=true -> evict-first loads for single-use weights
template<bool CS>
__device__ __forceinline__ float wdot(const float4* __restrict__ w,
                                      const float4* __restrict__ x,
                                      int n4, int lane) {
    float s0 = 0.f, s1 = 0.f, s2 = 0.f, s3 = 0.f;
#pragma unroll 4
    for (int i = lane; i < n4; i += 128) {
        float4 a0 = CS ? __ldcs(w + i)      : __ldg(w + i);
        float4 a1 = CS ? __ldcs(w + i + 32) : __ldg(w + i + 32);
        float4 a2 = CS ? __ldcs(w + i + 64) : __ldg(w + i + 64);
        float4 a3 = CS ? __ldcs(w + i + 96) : __ldg(w + i + 96);
        float4 b0 = x[i];
        float4 b1 = x[i + 32];
        float4 b2 = x[i + 64];
        float4 b3 = x[i + 96];
        s0 = fmaf(a0.x, b0.x, fmaf(a0.y, b0.y, fmaf(a0.z, b0.z, fmaf(a0.w, b0.w, s0))));
        s1 = fmaf(a1.x, b1.x, fmaf(a1.y, b1.y, fmaf(a1.z, b1.z, fmaf(a1.w, b1.w, s1))));
        s2 = fmaf(a2.x, b2.x, fmaf(a2.y, b2.y, fmaf(a2.z, b2.z, fmaf(a2.w, b2.w, s2))));
        s3 = fmaf(a3.x, b3.x, fmaf(a3.y, b3.y, fmaf(a3.z, b3.z, fmaf(a3.w, b3.w, s3))));
    }
    float s = (s0 + s1) + (s2 + s3);
#pragma unroll
    for (int o = 16; o; o >>= 1) s += __shfl_xor_sync(0xffffffffu, s, o);
    return s;
}

__global__ void __launch_bounds__(NT, 1)
decoder_kernel(const int* __restrict__ word, const float* __restrict__ lctx,
               const float* __restrict__ lh, const float* __restrict__ enc,
               const float* __restrict__ emb,
               const float* __restrict__ Wih0, const float* __restrict__ Whh0,
               const float* __restrict__ bih0, const float* __restrict__ bhh0,
               const float* __restrict__ Wih1, const float* __restrict__ Whh1,
               const float* __restrict__ bih1, const float* __restrict__ bhh1,
               const float* __restrict__ Wattn, const float* __restrict__ Wout,
               const float* __restrict__ bout, float* __restrict__ out) {
    __shared__ float sh_in[2 * H];
    __shared__ float sh_lh[2 * H];
    __shared__ float sh_h0[H];            // h0; later stages v
    __shared__ float sh_xcat[2 * H];      // [h1 ; ctx]
    __shared__ float sh_a[SCH];
    __shared__ float sh_red[32];
    __shared__ float sh_red2[32];
    __shared__ float sh_bc[2];
    __shared__ int   sh_t[2];             // double-buffered tile index

    const int t = threadIdx.x;
    const int lane = t & 31;
    const int wid = t >> 5;
    const int b = blockIdx.x;
    const int gw = b * 32 + wid;

    {
        int w0 = word[0];
        sh_in[t]     = emb[(size_t)w0 * H + t];
        sh_in[H + t] = lctx[t];
        sh_lh[t]     = lh[t];
        sh_lh[H + t] = lh[H + t];
    }
    if (b == 0) {
        g_v[t] = 0.f;
        g_ctx[t] = 0.f;
        if (t == 0) g_q = 0;              // first use after barrier 5 (proven safe in R12)
    }
    __syncthreads();

    // ---------- phase 1: equal 12KB units, one pass (static, proven) ------
    if (gw < G3) {
        float s = wdot<true>((const float4*)(Wih0 + (size_t)gw * 2 * H),
                             (const float4*)sh_in, 512, lane);
        if (!lane) g_gi0[gw] = s + bih0[gw];
        float s2 = wdot<true>((const float4*)(Whh0 + (size_t)gw * H),
                              (const float4*)sh_lh, 256, lane);
        if (!lane) g_gh0[gw] = s2 + bhh0[gw];
    } else if (gw < 4096) {
        int r0 = 3 * (gw - G3);
#pragma unroll
        for (int j = 0; j < 3; j++) {
            int r = r0 + j;
            float s = wdot<true>((const float4*)(Whh1 + (size_t)r * H),
                                 (const float4*)(sh_lh + H), 256, lane);
            if (!lane) g_gh1[r] = s + bhh1[r];
        }
    }
    gsync();   // barrier 1

    // ---------- phase 2: h0 recompute (local); gi1 = W_ih1 @ h0 ----------
    {
        float r_ = sigmoidf_(g_gi0[t] + g_gh0[t]);
        float z  = sigmoidf_(g_gi0[H + t] + g_gh0[H + t]);
        float n  = tanhf(g_gi0[2 * H + t] + r_ * g_gh0[2 * H + t]);
        float h  = (1.f - z) * n + z * sh_lh[t];
        sh_h0[t] = h;
        if (b == 0) out[V + H + t] = h;   // hidden[0]
    }
    __syncthreads();
    if (gw < G3) {
        float s = wdot<true>((const float4*)(Wih1 + (size_t)gw * H),
                             (const float4*)sh_h0, 256, lane);
        if (!lane) g_gi1[gw] = s + bih1[gw];
    }
    gsync();   // barrier 2

    // ---------- phase 3: h1 recompute (local); v partials -----------------
    {
        float r_ = sigmoidf_(g_gi1[t] + g_gh1[t]);
        float z  = sigmoidf_(g_gi1[H + t] + g_gh1[H + t]);
        float n  = tanhf(g_gi1[2 * H + t] + r_ * g_gh1[2 * H + t]);
        float h  = (1.f - z) * n + z * sh_lh[H + t];
        sh_xcat[t] = h;
        if (b == 0) out[V + 2 * H + t] = h; // hidden[1]
    }
    __syncthreads();
    {
        float acc = 0.f;
        int i0 = b * ICH;
#pragma unroll
        for (int k = 0; k < ICH; k++) {
            int i = i0 + k;
            if (i < H) acc = fmaf(Wattn[(size_t)i * H + t], sh_xcat[i], acc);
        }
        atomicAdd(&g_v[t], acc);
    }
    gsync();   // barrier 3

    // ---------- phase 4: energies (enc stays L2-resident: no .cs) ---------
    sh_h0[t] = g_v[t];
    __syncthreads();
    if (gw < S) {
        float s = wdot<false>((const float4*)(enc + (size_t)gw * H),
                              (const float4*)sh_h0, 256, lane);
        if (!lane) g_energ[gw] = s;
    }
    gsync();   // barrier 4

    // ---------- phase 5: softmax (redundant) + ctx partials ---------------
    {
        float m = -INFINITY;
        for (int i = t; i < S; i += NT) m = fmaxf(m, g_energ[i]);
#pragma unroll
        for (int o = 16; o; o >>= 1) m = fmaxf(m, __shfl_xor_sync(0xffffffffu, m, o));
        if (!lane) sh_red[wid] = m;
        __syncthreads();
        if (wid == 0) {
            m = sh_red[lane];
#pragma unroll
            for (int o = 16; o; o >>= 1) m = fmaxf(m, __shfl_xor_sync(0xffffffffu, m, o));
            if (!lane) sh_bc[0] = m;
        }
        __syncthreads();
        float bmax = sh_bc[0];
        float sum = 0.f;
        for (int i = t; i < S; i += NT) sum += __expf(g_energ[i] - bmax);
#pragma unroll
        for (int o = 16; o; o >>= 1) sum += __shfl_xor_sync(0xffffffffu, sum, o);
        if (!lane) sh_red[wid] = sum;
        __syncthreads();
        if (wid == 0) {
            sum = sh_red[lane];
#pragma unroll
            for (int o = 16; o; o >>= 1) sum += __shfl_xor_sync(0xffffffffu, sum, o);
            if (!lane) sh_bc[1] = sum;
        }
        __syncthreads();
        float inv = 1.f / sh_bc[1];
        int s0 = b * SCH;
        if (t < SCH && s0 + t < S) {
            float a = __expf(g_energ[s0 + t] - bmax) * inv;
            sh_a[t] = a;
            out[V + 3 * H + s0 + t] = a;  // attn_weights
        }
        __syncthreads();
        float acc = 0.f;
#pragma unroll
        for (int k = 0; k < SCH; k++) {
            int s = s0 + k;
            if (s < S) acc = fmaf(sh_a[k], enc[(size_t)s * H + t], acc);
        }
        atomicAdd(&g_ctx[t], acc);
    }
    gsync();   // barrier 5

    // ---------- phase 6: logits, block-tile queue w/ pop-ahead + LSE ------
    sh_xcat[H + t] = g_ctx[t];
    if (b == 0) out[V + t] = g_ctx[t];    // context
    __syncthreads();
    float lm = -INFINITY, lsum = 0.f;
    {
        if (t == 0) sh_t[0] = (int)atomicAdd(&g_q, 1u);
        __syncthreads();
        int buf = 0;
        int cur = sh_t[0];
        while (cur < NTILES6) {
            if (t == 0) sh_t[buf ^ 1] = (int)atomicAdd(&g_q, 1u); // hides under tile
            int r = cur * 32 + wid;      // 32 consecutive rows per block tile
            if (r < V) {
                float s = wdot<true>((const float4*)(Wout + (size_t)r * 2 * H),
                                     (const float4*)sh_xcat, 512, lane) + bout[r];
                if (!lane) g_logits[r] = s;
                float mn = fmaxf(lm, s);
                lsum = lsum * __expf(lm - mn) + __expf(s - mn);
                lm = mn;
            }
            __syncthreads();             // publishes next tile index
            buf ^= 1;
            cur = sh_t[buf];
        }
    }
    // block-level (max,sum) merge over 32 warps
    if (!lane) { sh_red[wid] = lm; sh_red2[wid] = lsum; }
    __syncthreads();
    if (wid == 0) {
        float m = sh_red[lane], sacc = sh_red2[lane];
#pragma unroll
        for (int o = 16; o; o >>= 1) {
            float mo = __shfl_xor_sync(0xffffffffu, m, o);
            float so = __shfl_xor_sync(0xffffffffu, sacc, o);
            float mn = fmaxf(m, mo);
            sacc = sacc * __expf(m - mn) + so * __expf(mo - mn);
            m = mn;
        }
        if (!lane) { g_part[2 * b] = m; g_part[2 * b + 1] = sacc; }
    }
    gsync();   // barrier 6

    // ---------- phase 7: merge LSE (redundant); write log_softmax ---------
    {
        if (wid == 0) {
            float m = -INFINITY, sacc = 0.f;
            for (int i = lane; i < NB; i += 32) {
                float mi = g_part[2 * i], si = g_part[2 * i + 1];
                float mn = fmaxf(m, mi);
                sacc = sacc * __expf(m - mn) + si * __expf(mi - mn);
                m = mn;
            }
#pragma unroll
            for (int o = 16; o; o >>= 1) {
                float mo = __shfl_xor_sync(0xffffffffu, m, o);
                float so = __shfl_xor_sync(0xffffffffu, sacc, o);
                float mn = fmaxf(m, mo);
                sacc = sacc * __expf(m - mn) + so * __expf(mo - mn);
                m = mn;
            }
            if (!lane) { sh_bc[0] = m; sh_bc[1] = logf(sacc); }
        }
        __syncthreads();
        float mm = sh_bc[0], ls = sh_bc[1];
        const int base = b * ROWS_PB;
        const int nrows = min(ROWS_PB, V - base);
        for (int i = t; i < nrows; i += NT)
            out[base + i] = g_logits[base + i] - mm - ls;
    }
}

// ---------------- launch ----------------
extern "C" void kernel_launch(void* const* d_in, const int* in_sizes, int n_in,
                              void* d_out, int out_size) {
    const int*   word  = (const int*)  d_in[0];
    const float* lctx  = (const float*)d_in[1];
    const float* lh    = (const float*)d_in[2];
    const float* enc   = (const float*)d_in[3];
    const float* emb   = (const float*)d_in[4];
    const float* Wih0  = (const float*)d_in[5];
    const float* Whh0  = (const float*)d_in[6];
    const float* bih0  = (const float*)d_in[7];
    const float* bhh0  = (const float*)d_in[8];
    const float* Wih1  = (const float*)d_in[9];
    const float* Whh1  = (const float*)d_in[10];
    const float* bih1  = (const float*)d_in[11];
    const float* bhh1  = (const float*)d_in[12];
    const float* Wattn = (const float*)d_in[13];
    // d_in[14] = b_attn: cancels in softmax
    const float* Wout  = (const float*)d_in[15];
    const float* bout  = (const float*)d_in[16];
    float* out = (float*)d_out;

    decoder_kernel<<<NB, NT>>>(word, lctx, lh, enc, emb,
                               Wih0, Whh0, bih0, bhh0,
                               Wih1, Whh1, bih1, bhh1,
                               Wattn, Wout, bout, out);
}